// round 3
// baseline (speedup 1.0000x reference)
#include <cuda_runtime.h>

#define NN 50000
#define NE 800000

// ---------------- scratch ----------------
__device__ __align__(16) float g_PQ  [NN * 512];   // [N,512]: P | Q
__device__ __align__(16) float g_agg [NN * 256];
__device__ __align__(16) float g_hmid[NN * 256];
__device__ __align__(16) float g_cnt [NN];
__device__ __align__(16) float g_csum[NN * 3];
__device__ __align__(16) float g_W1ab[512 * 256];
__device__ __align__(16) float g_wr  [256];
__device__ __align__(16) float g_b512[512];

// ---------------- helpers ----------------
__device__ __forceinline__ float siluf(float x) {
    return x * (1.0f / (1.0f + __expf(-x)));
}
__device__ __forceinline__ unsigned f2tf(float x) {
    unsigned r; asm("cvt.rna.tf32.f32 %0, %1;" : "=r"(r) : "f"(x)); return r;
}
__device__ __forceinline__ void mma8(float d[4], const unsigned a[4], const unsigned b[2]) {
    asm volatile(
        "mma.sync.aligned.m16n8k8.row.col.f32.tf32.tf32.f32 "
        "{%0,%1,%2,%3}, {%4,%5,%6,%7}, {%8,%9}, {%0,%1,%2,%3};\n"
        : "+f"(d[0]), "+f"(d[1]), "+f"(d[2]), "+f"(d[3])
        : "r"(a[0]), "r"(a[1]), "r"(a[2]), "r"(a[3]), "r"(b[0]), "r"(b[1]));
}
__device__ __forceinline__ void red4(float* p, float a, float b, float c, float d) {
    asm volatile("red.global.add.v4.f32 [%0], {%1,%2,%3,%4};"
                 :: "l"(p), "f"(a), "f"(b), "f"(c), "f"(d) : "memory");
}

// ---------------- small kernels ----------------
__global__ void pack_weights(const float* __restrict__ We1, const float* __restrict__ be1) {
    int i = blockIdx.x * blockDim.x + threadIdx.x;
    if (i < 512 * 256) {
        int n = i >> 8, k = i & 255;
        g_W1ab[i] = (n < 256) ? We1[n * 513 + k] : We1[(n - 256) * 513 + 256 + k];
    }
    if (i < 256) g_wr[i] = We1[i * 513 + 512];
    if (i < 512) g_b512[i] = (i < 256) ? be1[i] : 0.0f;
}

__global__ void zero_scratch() {
    int i = blockIdx.x * blockDim.x + threadIdx.x;
    if (i < NN * 256) g_agg[i] = 0.0f;
    if (i < NN * 3)   g_csum[i] = 0.0f;
    if (i < NN)       g_cnt[i] = 0.0f;
}

__global__ void coord_final_kernel(const float* __restrict__ coord, float* __restrict__ outc) {
    int i = blockIdx.x * blockDim.x + threadIdx.x;
    if (i >= NN) return;
    float d = fmaxf(g_cnt[i], 1.0f);
    outc[3 * i + 0] = coord[3 * i + 0] + g_csum[3 * i + 0] / d;
    outc[3 * i + 1] = coord[3 * i + 1] + g_csum[3 * i + 1] / d;
    outc[3 * i + 2] = coord[3 * i + 2] + g_csum[3 * i + 2] / d;
}

// =====================================================================
// Edge megakernel: per CTA (128 edges):
//   GEMM1: m = SiLU(P[r]+Q[c]+rad*wr)  (gathered on the fly)
//          ef = SiLU(m @ We2^T + be2)  -> SMEM (tf32), two 128-col phases
//   agg[r] += ef (red.v4)
//   GEMM2: s = ef @ Wc1^T ; phi = SiLU(s+bc1) . wc2
//   csum[r] += coord_diff * phi ; cnt[r] += 1
// =====================================================================
#define ESST 20    // smem stride (words) for A/B tiles (16 used)
#define EFST 260   // smem stride (words) for ef tile (256 used)
// smem words: Am 2*128*20=5120 | Bs 2*256*20=10240 | EF 128*260=33280 | sphi 128
#define MEGA_SMEM_WORDS (5120 + 10240 + 33280 + 128)

__global__ void __launch_bounds__(256, 1)
edge_mega(const int* __restrict__ ei, const float* __restrict__ coord,
          const float* __restrict__ We2, const float* __restrict__ be2,
          const float* __restrict__ Wc1, const float* __restrict__ bc1,
          const float* __restrict__ Wc2)
{
    extern __shared__ unsigned sm[];
    unsigned* Am = sm;                       // 2 x 128 x 20
    unsigned* Bs = sm + 5120;                // 2 x 256 x 20
    unsigned* EF = sm + 5120 + 10240;        // 128 x 260
    float* sphi  = (float*)(sm + 5120 + 10240 + 33280);

    const int tid  = threadIdx.x;
    const int lane = tid & 31;
    const int warp = tid >> 5;
    const int e0   = blockIdx.x * 128;
    const int lr   = tid >> 1;          // loader row 0..127
    const int lk   = (tid & 1) * 8;     // loader k offset 0/8

    const int er = ei[e0 + lr];
    const int ec = ei[NE + e0 + lr];
    const float dx = coord[3 * er + 0] - coord[3 * ec + 0];
    const float dy = coord[3 * er + 1] - coord[3 * ec + 1];
    const float dz = coord[3 * er + 2] - coord[3 * ec + 2];
    const float rad = dx * dx + dy * dy + dz * dz;

    if (tid < 128) sphi[tid] = 0.0f;

    const float* Pp = g_PQ + (size_t)er * 512;
    const float* Qp = g_PQ + (size_t)ec * 512 + 256;

    const int wm = (warp & 1) * 64;

    // ---------------- GEMM1: build ef tile in SMEM (two 128-col phases) ----------------
    for (int p = 0; p < 2; p++) {
        const int wn1 = (warp >> 1) * 32;
        const float* Wb = We2 + (size_t)(p * 128) * 256;   // this phase's 128 output rows

        float acc1[4][4][4];
#pragma unroll
        for (int i = 0; i < 4; i++)
#pragma unroll
            for (int j = 0; j < 4; j++)
#pragma unroll
                for (int q = 0; q < 4; q++) acc1[i][j][q] = 0.0f;

        float va[8], vb[8];
        // prologue: tile 0
        {
            float4 pa = *(const float4*)(Pp + lk);
            float4 pb = *(const float4*)(Pp + lk + 4);
            float4 qa = *(const float4*)(Qp + lk);
            float4 qb = *(const float4*)(Qp + lk + 4);
            float4 wa = *(const float4*)(g_wr + lk);
            float4 wc = *(const float4*)(g_wr + lk + 4);
            va[0] = pa.x + qa.x + rad * wa.x; va[1] = pa.y + qa.y + rad * wa.y;
            va[2] = pa.z + qa.z + rad * wa.z; va[3] = pa.w + qa.w + rad * wa.w;
            va[4] = pb.x + qb.x + rad * wc.x; va[5] = pb.y + qb.y + rad * wc.y;
            va[6] = pb.z + qb.z + rad * wc.z; va[7] = pb.w + qb.w + rad * wc.w;
            float4 b0 = *(const float4*)(Wb + (size_t)lr * 256 + lk);
            float4 b1 = *(const float4*)(Wb + (size_t)lr * 256 + lk + 4);
            vb[0] = b0.x; vb[1] = b0.y; vb[2] = b0.z; vb[3] = b0.w;
            vb[4] = b1.x; vb[5] = b1.y; vb[6] = b1.z; vb[7] = b1.w;
            uint4 t0, t1;
            t0.x = f2tf(siluf(va[0])); t0.y = f2tf(siluf(va[1])); t0.z = f2tf(siluf(va[2])); t0.w = f2tf(siluf(va[3]));
            t1.x = f2tf(siluf(va[4])); t1.y = f2tf(siluf(va[5])); t1.z = f2tf(siluf(va[6])); t1.w = f2tf(siluf(va[7]));
            *(uint4*)(Am + lr * ESST + lk) = t0;
            *(uint4*)(Am + lr * ESST + lk + 4) = t1;
            uint4 s0, s1;
            s0.x = f2tf(vb[0]); s0.y = f2tf(vb[1]); s0.z = f2tf(vb[2]); s0.w = f2tf(vb[3]);
            s1.x = f2tf(vb[4]); s1.y = f2tf(vb[5]); s1.z = f2tf(vb[6]); s1.w = f2tf(vb[7]);
            *(uint4*)(Bs + lr * ESST + lk) = s0;
            *(uint4*)(Bs + lr * ESST + lk + 4) = s1;
        }
        __syncthreads();

#pragma unroll 1
        for (int kt = 0; kt < 16; kt++) {
            if (kt < 15) {
                const int k0 = (kt + 1) * 16;
                float4 pa = *(const float4*)(Pp + k0 + lk);
                float4 pb = *(const float4*)(Pp + k0 + lk + 4);
                float4 qa = *(const float4*)(Qp + k0 + lk);
                float4 qb = *(const float4*)(Qp + k0 + lk + 4);
                float4 wa = *(const float4*)(g_wr + k0 + lk);
                float4 wc = *(const float4*)(g_wr + k0 + lk + 4);
                va[0] = pa.x + qa.x + rad * wa.x; va[1] = pa.y + qa.y + rad * wa.y;
                va[2] = pa.z + qa.z + rad * wa.z; va[3] = pa.w + qa.w + rad * wa.w;
                va[4] = pb.x + qb.x + rad * wc.x; va[5] = pb.y + qb.y + rad * wc.y;
                va[6] = pb.z + qb.z + rad * wc.z; va[7] = pb.w + qb.w + rad * wc.w;
                float4 b0 = *(const float4*)(Wb + (size_t)lr * 256 + k0 + lk);
                float4 b1 = *(const float4*)(Wb + (size_t)lr * 256 + k0 + lk + 4);
                vb[0] = b0.x; vb[1] = b0.y; vb[2] = b0.z; vb[3] = b0.w;
                vb[4] = b1.x; vb[5] = b1.y; vb[6] = b1.z; vb[7] = b1.w;
            }
            const unsigned* As = Am + (kt & 1) * 2560;
            const unsigned* Bb = Bs + (kt & 1) * 5120;
#pragma unroll
            for (int kk = 0; kk < 16; kk += 8) {
                unsigned af[4][4];
#pragma unroll
                for (int mt = 0; mt < 4; mt++) {
                    int r = wm + mt * 16 + (lane >> 2);
                    int c = kk + (lane & 3);
                    af[mt][0] = As[r * ESST + c];
                    af[mt][1] = As[(r + 8) * ESST + c];
                    af[mt][2] = As[r * ESST + c + 4];
                    af[mt][3] = As[(r + 8) * ESST + c + 4];
                }
                unsigned bf[4][2];
#pragma unroll
                for (int nt = 0; nt < 4; nt++) {
                    int n = wn1 + nt * 8 + (lane >> 2);
                    int c = kk + (lane & 3);
                    bf[nt][0] = Bb[n * ESST + c];
                    bf[nt][1] = Bb[n * ESST + c + 4];
                }
#pragma unroll
                for (int mt = 0; mt < 4; mt++)
#pragma unroll
                    for (int nt = 0; nt < 4; nt++)
                        mma8(acc1[mt][nt], af[mt], bf[nt]);
            }
            if (kt < 15) {
                unsigned* Aw = Am + ((kt + 1) & 1) * 2560;
                unsigned* Bw = Bs + ((kt + 1) & 1) * 5120;
                uint4 t0, t1;
                t0.x = f2tf(siluf(va[0])); t0.y = f2tf(siluf(va[1])); t0.z = f2tf(siluf(va[2])); t0.w = f2tf(siluf(va[3]));
                t1.x = f2tf(siluf(va[4])); t1.y = f2tf(siluf(va[5])); t1.z = f2tf(siluf(va[6])); t1.w = f2tf(siluf(va[7]));
                *(uint4*)(Aw + lr * ESST + lk) = t0;
                *(uint4*)(Aw + lr * ESST + lk + 4) = t1;
                uint4 s0, s1;
                s0.x = f2tf(vb[0]); s0.y = f2tf(vb[1]); s0.z = f2tf(vb[2]); s0.w = f2tf(vb[3]);
                s1.x = f2tf(vb[4]); s1.y = f2tf(vb[5]); s1.z = f2tf(vb[6]); s1.w = f2tf(vb[7]);
                *(uint4*)(Bw + lr * ESST + lk) = s0;
                *(uint4*)(Bw + lr * ESST + lk + 4) = s1;
                __syncthreads();
            }
        }

        // phase epilogue: SiLU(+be2) -> EF smem (tf32)
#pragma unroll
        for (int mt = 0; mt < 4; mt++) {
#pragma unroll
            for (int h2 = 0; h2 < 2; h2++) {
                int row = wm + mt * 16 + (lane >> 2) + h2 * 8;
#pragma unroll
                for (int nt = 0; nt < 4; nt++) {
#pragma unroll
                    for (int q = 0; q < 2; q++) {
                        int col = p * 128 + wn1 + nt * 8 + (lane & 3) * 2 + q;
                        float v = siluf(acc1[mt][nt][h2 * 2 + q] + be2[col]);
                        EF[row * EFST + col] = f2tf(v);
                    }
                }
            }
        }
        __syncthreads();
    }

    // ---------------- agg scatter (vector red) ----------------
    {
        const float* efr = (const float*)(EF + lr * EFST) + (tid & 1) * 128;
        float* dst = g_agg + (size_t)er * 256 + (tid & 1) * 128;
#pragma unroll
        for (int j = 0; j < 32; j++) {
            float4 v = *(const float4*)(efr + j * 4);
            red4(dst + j * 4, v.x, v.y, v.z, v.w);
        }
    }

    // ---------------- GEMM2: s = ef @ Wc1^T ----------------
    const int wn2 = (warp >> 1) * 64;
    float acc2[4][8][4];
#pragma unroll
    for (int i = 0; i < 4; i++)
#pragma unroll
        for (int j = 0; j < 8; j++)
#pragma unroll
            for (int q = 0; q < 4; q++) acc2[i][j][q] = 0.0f;

    float vb2[16];
    // prologue: Wc1 tile 0 (256 rows x 16 k)
    {
        float4 b0 = *(const float4*)(Wc1 + (size_t)lr * 256 + lk);
        float4 b1 = *(const float4*)(Wc1 + (size_t)lr * 256 + lk + 4);
        float4 b2 = *(const float4*)(Wc1 + (size_t)(lr + 128) * 256 + lk);
        float4 b3 = *(const float4*)(Wc1 + (size_t)(lr + 128) * 256 + lk + 4);
        vb2[0] = b0.x; vb2[1] = b0.y; vb2[2] = b0.z; vb2[3] = b0.w;
        vb2[4] = b1.x; vb2[5] = b1.y; vb2[6] = b1.z; vb2[7] = b1.w;
        vb2[8] = b2.x; vb2[9] = b2.y; vb2[10] = b2.z; vb2[11] = b2.w;
        vb2[12] = b3.x; vb2[13] = b3.y; vb2[14] = b3.z; vb2[15] = b3.w;
        uint4 s0, s1, s2, s3;
        s0.x = f2tf(vb2[0]);  s0.y = f2tf(vb2[1]);  s0.z = f2tf(vb2[2]);  s0.w = f2tf(vb2[3]);
        s1.x = f2tf(vb2[4]);  s1.y = f2tf(vb2[5]);  s1.z = f2tf(vb2[6]);  s1.w = f2tf(vb2[7]);
        s2.x = f2tf(vb2[8]);  s2.y = f2tf(vb2[9]);  s2.z = f2tf(vb2[10]); s2.w = f2tf(vb2[11]);
        s3.x = f2tf(vb2[12]); s3.y = f2tf(vb2[13]); s3.z = f2tf(vb2[14]); s3.w = f2tf(vb2[15]);
        *(uint4*)(Bs + lr * ESST + lk) = s0;
        *(uint4*)(Bs + lr * ESST + lk + 4) = s1;
        *(uint4*)(Bs + (lr + 128) * ESST + lk) = s2;
        *(uint4*)(Bs + (lr + 128) * ESST + lk + 4) = s3;
    }
    __syncthreads();

#pragma unroll 1
    for (int kt = 0; kt < 16; kt++) {
        if (kt < 15) {
            const int k0 = (kt + 1) * 16;
            float4 b0 = *(const float4*)(Wc1 + (size_t)lr * 256 + k0 + lk);
            float4 b1 = *(const float4*)(Wc1 + (size_t)lr * 256 + k0 + lk + 4);
            float4 b2 = *(const float4*)(Wc1 + (size_t)(lr + 128) * 256 + k0 + lk);
            float4 b3 = *(const float4*)(Wc1 + (size_t)(lr + 128) * 256 + k0 + lk + 4);
            vb2[0] = b0.x; vb2[1] = b0.y; vb2[2] = b0.z; vb2[3] = b0.w;
            vb2[4] = b1.x; vb2[5] = b1.y; vb2[6] = b1.z; vb2[7] = b1.w;
            vb2[8] = b2.x; vb2[9] = b2.y; vb2[10] = b2.z; vb2[11] = b2.w;
            vb2[12] = b3.x; vb2[13] = b3.y; vb2[14] = b3.z; vb2[15] = b3.w;
        }
        const unsigned* Bb = Bs + (kt & 1) * 5120;
#pragma unroll
        for (int kk = 0; kk < 16; kk += 8) {
            unsigned af[4][4];
#pragma unroll
            for (int mt = 0; mt < 4; mt++) {
                int r = wm + mt * 16 + (lane >> 2);
                int c = kt * 16 + kk + (lane & 3);
                af[mt][0] = EF[r * EFST + c];
                af[mt][1] = EF[(r + 8) * EFST + c];
                af[mt][2] = EF[r * EFST + c + 4];
                af[mt][3] = EF[(r + 8) * EFST + c + 4];
            }
            unsigned bf[8][2];
#pragma unroll
            for (int nt = 0; nt < 8; nt++) {
                int n = wn2 + nt * 8 + (lane >> 2);
                int c = kk + (lane & 3);
                bf[nt][0] = Bb[n * ESST + c];
                bf[nt][1] = Bb[n * ESST + c + 4];
            }
#pragma unroll
            for (int mt = 0; mt < 4; mt++)
#pragma unroll
                for (int nt = 0; nt < 8; nt++)
                    mma8(acc2[mt][nt], af[mt], bf[nt]);
        }
        if (kt < 15) {
            unsigned* Bw = Bs + ((kt + 1) & 1) * 5120;
            uint4 s0, s1, s2, s3;
            s0.x = f2tf(vb2[0]);  s0.y = f2tf(vb2[1]);  s0.z = f2tf(vb2[2]);  s0.w = f2tf(vb2[3]);
            s1.x = f2tf(vb2[4]);  s1.y = f2tf(vb2[5]);  s1.z = f2tf(vb2[6]);  s1.w = f2tf(vb2[7]);
            s2.x = f2tf(vb2[8]);  s2.y = f2tf(vb2[9]);  s2.z = f2tf(vb2[10]); s2.w = f2tf(vb2[11]);
            s3.x = f2tf(vb2[12]); s3.y = f2tf(vb2[13]); s3.z = f2tf(vb2[14]); s3.w = f2tf(vb2[15]);
            *(uint4*)(Bw + lr * ESST + lk) = s0;
            *(uint4*)(Bw + lr * ESST + lk + 4) = s1;
            *(uint4*)(Bw + (lr + 128) * ESST + lk) = s2;
            *(uint4*)(Bw + (lr + 128) * ESST + lk + 4) = s3;
            __syncthreads();
        }
    }

    // ---------------- epilogue2: phi = SiLU(s+bc1) . wc2 ----------------
#pragma unroll
    for (int mt = 0; mt < 4; mt++) {
#pragma unroll
        for (int h2 = 0; h2 < 2; h2++) {
            int row = wm + mt * 16 + (lane >> 2) + h2 * 8;  // local 0..127
            float pp = 0.0f;
#pragma unroll
            for (int nt = 0; nt < 8; nt++) {
#pragma unroll
                for (int q = 0; q < 2; q++) {
                    int col = wn2 + nt * 8 + (lane & 3) * 2 + q;
                    float v = siluf(acc2[mt][nt][h2 * 2 + q] + bc1[col]);
                    pp += v * Wc2[col];
                }
            }
            pp += __shfl_xor_sync(0xffffffffu, pp, 1);
            pp += __shfl_xor_sync(0xffffffffu, pp, 2);
            if ((lane & 3) == 0) atomicAdd(&sphi[row], pp);
        }
    }
    __syncthreads();

    if (tid < 128) {
        float phi = sphi[tid];
        int r2 = ei[e0 + tid], c2 = ei[NE + e0 + tid];
        float ddx = coord[3 * r2 + 0] - coord[3 * c2 + 0];
        float ddy = coord[3 * r2 + 1] - coord[3 * c2 + 1];
        float ddz = coord[3 * r2 + 2] - coord[3 * c2 + 2];
        atomicAdd(&g_csum[3 * r2 + 0], ddx * phi);
        atomicAdd(&g_csum[3 * r2 + 1], ddy * phi);
        atomicAdd(&g_csum[3 * r2 + 2], ddz * phi);
        atomicAdd(&g_cnt[r2], 1.0f);
    }
}

// ---------------- node GEMM (from round 1, node-side modes only) ----------------
#define BM 128
#define BN 256
#define BK 32
#define SST 36

enum { MODE_PLAIN = 0, MODE_CAT = 3, MODE_NODE2 = 4 };

template <int MODE>
__global__ void __launch_bounds__(256, 1)
gemm_kernel(const float* __restrict__ A, const float* __restrict__ A2,
            const float* __restrict__ W, const float* __restrict__ bias,
            float* __restrict__ C, int ldc, int M, int K,
            const float* __restrict__ resid)
{
    extern __shared__ unsigned smem[];
    unsigned* Abase = smem;
    unsigned* Bbase = smem + 2 * BM * SST;

    const int tid  = threadIdx.x;
    const int lane = tid & 31;
    const int warp = tid >> 5;
    const int wm = (warp & 1) * 64;
    const int wn = (warp >> 1) * 64;
    const int blockM = blockIdx.x * BM;
    const int blockN = blockIdx.y * BN;
    const int ldr = tid >> 3;
    const int lkq = (tid & 7) * 4;

    float acc[4][8][4];
#pragma unroll
    for (int i = 0; i < 4; i++)
#pragma unroll
        for (int j = 0; j < 8; j++)
#pragma unroll
            for (int q = 0; q < 4; q++) acc[i][j][q] = 0.0f;

    float4 ra[4];
    float4 rb[8];
    const int ktiles = K / BK;

    {
        const int k0 = 0;
#pragma unroll
        for (int i = 0; i < 4; i++) {
            int r = blockM + ldr + i * 32;
            const float* s;
            if (MODE == MODE_CAT)
                s = (k0 + lkq < 256) ? (A + (size_t)r * 256 + k0 + lkq)
                                     : (A2 + (size_t)r * 256 + (k0 + lkq - 256));
            else
                s = A + (size_t)r * K + k0 + lkq;
            ra[i] = (r < M) ? *(const float4*)s : make_float4(0, 0, 0, 0);
        }
#pragma unroll
        for (int i = 0; i < 8; i++) {
            int n = blockN + ldr + i * 32;
            rb[i] = *(const float4*)(W + (size_t)n * K + k0 + lkq);
        }
        unsigned* as = Abase;
        unsigned* bs = Bbase;
#pragma unroll
        for (int i = 0; i < 4; i++) {
            uint4 t; t.x = f2tf(ra[i].x); t.y = f2tf(ra[i].y); t.z = f2tf(ra[i].z); t.w = f2tf(ra[i].w);
            *(uint4*)(as + (ldr + i * 32) * SST + lkq) = t;
        }
#pragma unroll
        for (int i = 0; i < 8; i++) {
            uint4 t; t.x = f2tf(rb[i].x); t.y = f2tf(rb[i].y); t.z = f2tf(rb[i].z); t.w = f2tf(rb[i].w);
            *(uint4*)(bs + (ldr + i * 32) * SST + lkq) = t;
        }
    }
    __syncthreads();

    for (int t = 0; t < ktiles; ++t) {
        if (t + 1 < ktiles) {
            const int k0 = (t + 1) * BK;
#pragma unroll
            for (int i = 0; i < 4; i++) {
                int r = blockM + ldr + i * 32;
                const float* s;
                if (MODE == MODE_CAT)
                    s = (k0 + lkq < 256) ? (A + (size_t)r * 256 + k0 + lkq)
                                         : (A2 + (size_t)r * 256 + (k0 + lkq - 256));
                else
                    s = A + (size_t)r * K + k0 + lkq;
                ra[i] = (r < M) ? *(const float4*)s : make_float4(0, 0, 0, 0);
            }
#pragma unroll
            for (int i = 0; i < 8; i++) {
                int n = blockN + ldr + i * 32;
                rb[i] = *(const float4*)(W + (size_t)n * K + k0 + lkq);
            }
        }
        const unsigned* as = Abase + (t & 1) * BM * SST;
        const unsigned* bs = Bbase + (t & 1) * BN * SST;
#pragma unroll
        for (int kk = 0; kk < BK; kk += 8) {
            unsigned af[4][4];
#pragma unroll
            for (int mt = 0; mt < 4; mt++) {
                int r = wm + mt * 16 + (lane >> 2);
                int c = kk + (lane & 3);
                af[mt][0] = as[r * SST + c];
                af[mt][1] = as[(r + 8) * SST + c];
                af[mt][2] = as[r * SST + c + 4];
                af[mt][3] = as[(r + 8) * SST + c + 4];
            }
            unsigned bf[8][2];
#pragma unroll
            for (int nt = 0; nt < 8; nt++) {
                int n = wn + nt * 8 + (lane >> 2);
                int c = kk + (lane & 3);
                bf[nt][0] = bs[n * SST + c];
                bf[nt][1] = bs[n * SST + c + 4];
            }
#pragma unroll
            for (int mt = 0; mt < 4; mt++)
#pragma unroll
                for (int nt = 0; nt < 8; nt++)
                    mma8(acc[mt][nt], af[mt], bf[nt]);
        }
        if (t + 1 < ktiles) {
            unsigned* asw = Abase + ((t + 1) & 1) * BM * SST;
            unsigned* bsw = Bbase + ((t + 1) & 1) * BN * SST;
#pragma unroll
            for (int i = 0; i < 4; i++) {
                uint4 tt; tt.x = f2tf(ra[i].x); tt.y = f2tf(ra[i].y); tt.z = f2tf(ra[i].z); tt.w = f2tf(ra[i].w);
                *(uint4*)(asw + (ldr + i * 32) * SST + lkq) = tt;
            }
#pragma unroll
            for (int i = 0; i < 8; i++) {
                uint4 tt; tt.x = f2tf(rb[i].x); tt.y = f2tf(rb[i].y); tt.z = f2tf(rb[i].z); tt.w = f2tf(rb[i].w);
                *(uint4*)(bsw + (ldr + i * 32) * SST + lkq) = tt;
            }
            __syncthreads();
        }
    }

#pragma unroll
    for (int mt = 0; mt < 4; mt++) {
#pragma unroll
        for (int h2 = 0; h2 < 2; h2++) {
            int row = blockM + wm + mt * 16 + (lane >> 2) + h2 * 8;
            if (row < M) {
#pragma unroll
                for (int nt = 0; nt < 8; nt++) {
                    int col = blockN + wn + nt * 8 + (lane & 3) * 2;
                    float v0 = acc[mt][nt][h2 * 2 + 0];
                    float v1 = acc[mt][nt][h2 * 2 + 1];
                    if (MODE == MODE_PLAIN) {
                        v0 += bias[col]; v1 += bias[col + 1];
                        *(float2*)&C[(size_t)row * ldc + col] = make_float2(v0, v1);
                    } else if (MODE == MODE_CAT) {
                        v0 = siluf(v0 + bias[col]);
                        v1 = siluf(v1 + bias[col + 1]);
                        *(float2*)&C[(size_t)row * ldc + col] = make_float2(v0, v1);
                    } else {  // MODE_NODE2
                        v0 += bias[col] + resid[(size_t)row * ldc + col];
                        v1 += bias[col + 1] + resid[(size_t)row * ldc + col + 1];
                        *(float2*)&C[(size_t)row * ldc + col] = make_float2(v0, v1);
                    }
                }
            }
        }
    }
}

// ---------------- host ----------------
extern "C" void kernel_launch(void* const* d_in, const int* in_sizes, int n_in,
                              void* d_out, int out_size)
{
    (void)in_sizes; (void)n_in; (void)out_size;
    const float* h     = (const float*)d_in[0];
    const int*   ei    = (const int*)  d_in[1];
    const float* coord = (const float*)d_in[2];
    const float* We1   = (const float*)d_in[3];
    const float* be1   = (const float*)d_in[4];
    const float* We2   = (const float*)d_in[5];
    const float* be2   = (const float*)d_in[6];
    const float* Wn1   = (const float*)d_in[7];
    const float* bn1   = (const float*)d_in[8];
    const float* Wn2   = (const float*)d_in[9];
    const float* bn2   = (const float*)d_in[10];
    const float* Wc1   = (const float*)d_in[11];
    const float* bc1   = (const float*)d_in[12];
    const float* Wc2   = (const float*)d_in[13];
    float* outh = (float*)d_out;
    float* outc = outh + (size_t)NN * 256;

    float *pPQ, *phmid, *pagg, *pW1ab, *pb512;
    cudaGetSymbolAddress((void**)&pPQ,   g_PQ);
    cudaGetSymbolAddress((void**)&phmid, g_hmid);
    cudaGetSymbolAddress((void**)&pagg,  g_agg);
    cudaGetSymbolAddress((void**)&pW1ab, g_W1ab);
    cudaGetSymbolAddress((void**)&pb512, g_b512);

    const int SMEMB = (2 * BM * SST + 2 * BN * SST) * 4;
    const int MSMEMB = MEGA_SMEM_WORDS * 4;
    cudaFuncSetAttribute((const void*)gemm_kernel<MODE_PLAIN>, cudaFuncAttributeMaxDynamicSharedMemorySize, SMEMB);
    cudaFuncSetAttribute((const void*)gemm_kernel<MODE_CAT>,   cudaFuncAttributeMaxDynamicSharedMemorySize, SMEMB);
    cudaFuncSetAttribute((const void*)gemm_kernel<MODE_NODE2>, cudaFuncAttributeMaxDynamicSharedMemorySize, SMEMB);
    cudaFuncSetAttribute((const void*)edge_mega, cudaFuncAttributeMaxDynamicSharedMemorySize, MSMEMB);

    pack_weights<<<512, 256>>>(We1, be1);
    zero_scratch<<<50000, 256>>>();

    // PQ = h @ [We1a;We1b]^T + [be1;0]
    gemm_kernel<MODE_PLAIN><<<dim3((NN + BM - 1) / BM, 2), 256, SMEMB>>>(
        h, nullptr, pW1ab, pb512, pPQ, 512, NN, 256, nullptr);

    // fused edge pipeline
    edge_mega<<<NE / 128, 256, MSMEMB>>>(ei, coord, We2, be2, Wc1, bc1, Wc2);

    coord_final_kernel<<<(NN + 255) / 256, 256>>>(coord, outc);

    // hmid = SiLU([h | agg] @ Wn1^T + bn1)
    gemm_kernel<MODE_CAT><<<dim3((NN + BM - 1) / BM, 1), 256, SMEMB>>>(
        h, pagg, Wn1, bn1, phmid, 256, NN, 512, nullptr);

    // h_out = hmid @ Wn2^T + bn2 + h
    gemm_kernel<MODE_NODE2><<<dim3((NN + BM - 1) / BM, 1), 256, SMEMB>>>(
        phmid, nullptr, Wn2, bn2, outh, 256, NN, 256, h);
}

// round 4
// speedup vs baseline: 1.7038x; 1.7038x over previous
#include <cuda_runtime.h>

#define NN 50000
#define NE 800000

// ---------------- scratch ----------------
__device__ __align__(16) float g_PQ  [NN * 512];   // [N,512]: P | Q
__device__ __align__(16) float g_m   [NE * 256];   // edge hidden (tf32 bits)
__device__ __align__(16) float g_ef  [NE * 256];   // edge features (tf32 bits)
__device__ __align__(16) float g_agg [NN * 256];
__device__ __align__(16) float g_hmid[NN * 256];
__device__ __align__(16) float g_phi [NE];
__device__ __align__(16) float g_cnt [NN];
__device__ __align__(16) float g_csum[NN * 3];
__device__ __align__(16) float g_W1ab[512 * 256];
__device__ __align__(16) float g_We2t[256 * 256];  // tf32 bits
__device__ __align__(16) float g_Wc1t[256 * 256];  // tf32 bits
__device__ __align__(16) float g_wr  [256];
__device__ __align__(16) float g_b512[512];

// ---------------- helpers ----------------
__device__ __forceinline__ float siluf(float x) {
    return x * (1.0f / (1.0f + __expf(-x)));
}
__device__ __forceinline__ unsigned f2tf(float x) {
    unsigned r; asm("cvt.rna.tf32.f32 %0, %1;" : "=r"(r) : "f"(x)); return r;
}
__device__ __forceinline__ void mma8(float d[4], const unsigned a[4], const unsigned b[2]) {
    asm volatile(
        "mma.sync.aligned.m16n8k8.row.col.f32.tf32.tf32.f32 "
        "{%0,%1,%2,%3}, {%4,%5,%6,%7}, {%8,%9}, {%0,%1,%2,%3};\n"
        : "+f"(d[0]), "+f"(d[1]), "+f"(d[2]), "+f"(d[3])
        : "r"(a[0]), "r"(a[1]), "r"(a[2]), "r"(a[3]), "r"(b[0]), "r"(b[1]));
}
__device__ __forceinline__ void red2(float* p, float a, float b) {
    asm volatile("red.global.add.v2.f32 [%0], {%1,%2};"
                 :: "l"(p), "f"(a), "f"(b) : "memory");
}
__device__ __forceinline__ void cpa16(unsigned saddr, const float* g) {
    asm volatile("cp.async.cg.shared.global [%0], [%1], 16;" :: "r"(saddr), "l"(g));
}

// ---------------- small kernels ----------------
__global__ void pack_weights(const float* __restrict__ We1, const float* __restrict__ be1,
                             const float* __restrict__ We2, const float* __restrict__ Wc1) {
    int i = blockIdx.x * blockDim.x + threadIdx.x;
    if (i < 512 * 256) {
        int n = i >> 8, k = i & 255;
        g_W1ab[i] = (n < 256) ? We1[n * 513 + k] : We1[(n - 256) * 513 + 256 + k];
    }
    if (i < 256 * 256) {
        g_We2t[i] = __uint_as_float(f2tf(We2[i]));
        g_Wc1t[i] = __uint_as_float(f2tf(Wc1[i]));
    }
    if (i < 256) g_wr[i] = We1[i * 513 + 512];
    if (i < 512) g_b512[i] = (i < 256) ? be1[i] : 0.0f;
}

__global__ void zero_scratch() {
    int i = blockIdx.x * blockDim.x + threadIdx.x;
    if (i < NN * 256) g_agg[i] = 0.0f;
    if (i < NE)       g_phi[i] = 0.0f;
    if (i < NN * 3)   g_csum[i] = 0.0f;
    if (i < NN)       g_cnt[i] = 0.0f;
}

// one warp per edge: m = tf32(SiLU(P[row] + Q[col] + radial*wr))
__global__ void edge_m_kernel(const int* __restrict__ ei, const float* __restrict__ coord) {
    int e = blockIdx.x * 8 + (threadIdx.x >> 5);
    if (e >= NE) return;
    int lane = threadIdx.x & 31;
    int r = ei[e];
    int c = ei[NE + e];
    float dx = coord[3 * r + 0] - coord[3 * c + 0];
    float dy = coord[3 * r + 1] - coord[3 * c + 1];
    float dz = coord[3 * r + 2] - coord[3 * c + 2];
    float rad = dx * dx + dy * dy + dz * dz;
    const float4* PQ4 = (const float4*)g_PQ;
    const float4* wr4 = (const float4*)g_wr;
    float4* m4 = (float4*)g_m;
#pragma unroll
    for (int it = 0; it < 2; it++) {
        int q = lane + it * 32;
        float4 p  = PQ4[(size_t)r * 128 + q];
        float4 qq = PQ4[(size_t)c * 128 + 64 + q];
        float4 w  = wr4[q];
        float4 v;
        v.x = __uint_as_float(f2tf(siluf(p.x + qq.x + rad * w.x)));
        v.y = __uint_as_float(f2tf(siluf(p.y + qq.y + rad * w.y)));
        v.z = __uint_as_float(f2tf(siluf(p.z + qq.z + rad * w.z)));
        v.w = __uint_as_float(f2tf(siluf(p.w + qq.w + rad * w.w)));
        m4[(size_t)e * 64 + q] = v;
    }
    if (lane == 0) atomicAdd(&g_cnt[r], 1.0f);
}

__global__ void edge_coord_kernel(const int* __restrict__ ei, const float* __restrict__ coord) {
    int e = blockIdx.x * blockDim.x + threadIdx.x;
    if (e >= NE) return;
    int r = ei[e], c = ei[NE + e];
    float p = g_phi[e];
    atomicAdd(&g_csum[3 * r + 0], (coord[3 * r + 0] - coord[3 * c + 0]) * p);
    atomicAdd(&g_csum[3 * r + 1], (coord[3 * r + 1] - coord[3 * c + 1]) * p);
    atomicAdd(&g_csum[3 * r + 2], (coord[3 * r + 2] - coord[3 * c + 2]) * p);
}

__global__ void coord_final_kernel(const float* __restrict__ coord, float* __restrict__ outc) {
    int i = blockIdx.x * blockDim.x + threadIdx.x;
    if (i >= NN) return;
    float d = fmaxf(g_cnt[i], 1.0f);
    outc[3 * i + 0] = coord[3 * i + 0] + g_csum[3 * i + 0] / d;
    outc[3 * i + 1] = coord[3 * i + 1] + g_csum[3 * i + 1] / d;
    outc[3 * i + 2] = coord[3 * i + 2] + g_csum[3 * i + 2] / d;
}

// =====================================================================
// Async-pipelined edge GEMM: C = epilogue(A[NE,256] @ W[256,256]^T)
// A, W already tf32 bits in memory -> pure cp.async mainloop, 3 stages.
//   MODE EF : ef = tf32(SiLU(acc+be2)); agg[rowidx] += SiLU vals (red.v2)
//   MODE PHI: phi[row] = sum_col SiLU(acc+bc1)*wc2[col]
// =====================================================================
#define PST 36            // padded stride (words)
#define STG_A (128 * PST) // 4608 words
#define STG_B (256 * PST) // 9216 words
#define STG_W (STG_A + STG_B)
#define ESMEM_WORDS (3 * STG_W)

enum { EMODE_EF = 0, EMODE_PHI = 1 };

template <int MODE>
__global__ void __launch_bounds__(256, 1)
egemm(const float* __restrict__ A, const float* __restrict__ W,
      const float* __restrict__ bias, float* __restrict__ C,
      const int* __restrict__ rowidx, float* __restrict__ agg,
      const float* __restrict__ wc2, float* __restrict__ phi)
{
    extern __shared__ float esm[];
    const int tid  = threadIdx.x;
    const int lane = tid & 31;
    const int warp = tid >> 5;
    const int wm = (warp & 1) * 64;
    const int wn = (warp >> 1) * 64;
    const int blockM = blockIdx.x * 128;
    const unsigned sbase = (unsigned)__cvta_generic_to_shared(esm);

    float acc[4][8][4];
#pragma unroll
    for (int i = 0; i < 4; i++)
#pragma unroll
        for (int j = 0; j < 8; j++)
#pragma unroll
            for (int q = 0; q < 4; q++) acc[i][j][q] = 0.0f;

    // loader lambda inlined manually
#define ISSUE_TILE(stage, k0)                                                        \
    do {                                                                             \
        _Pragma("unroll")                                                            \
        for (int i = 0; i < 4; i++) {                                                \
            int ch = tid + i * 256;                                                  \
            int r = ch >> 3, c = (ch & 7) * 4;                                       \
            cpa16(sbase + ((stage) * STG_W + r * PST + c) * 4,                       \
                  A + (size_t)(blockM + r) * 256 + (k0) + c);                        \
        }                                                                            \
        _Pragma("unroll")                                                            \
        for (int i = 0; i < 8; i++) {                                                \
            int ch = tid + i * 256;                                                  \
            int r = ch >> 3, c = (ch & 7) * 4;                                       \
            cpa16(sbase + ((stage) * STG_W + STG_A + r * PST + c) * 4,               \
                  W + (size_t)r * 256 + (k0) + c);                                   \
        }                                                                            \
        asm volatile("cp.async.commit_group;");                                      \
    } while (0)

    ISSUE_TILE(0, 0);
    ISSUE_TILE(1, 32);

#pragma unroll 1
    for (int kt = 0; kt < 8; kt++) {
        __syncthreads();  // stage (kt+2)%3 no longer being read by any thread
        if (kt + 2 < 8) {
            ISSUE_TILE((kt + 2) % 3, (kt + 2) * 32);
            asm volatile("cp.async.wait_group 2;");
        } else if (kt + 1 < 8) {
            asm volatile("cp.async.wait_group 1;");
        } else {
            asm volatile("cp.async.wait_group 0;");
        }
        __syncthreads();  // publish completed stage to all threads

        const unsigned* as = (const unsigned*)(esm + (kt % 3) * STG_W);
        const unsigned* bs = as + STG_A;
#pragma unroll
        for (int kk = 0; kk < 32; kk += 8) {
            unsigned af[4][4];
#pragma unroll
            for (int mt = 0; mt < 4; mt++) {
                int r = wm + mt * 16 + (lane >> 2);
                int c = kk + (lane & 3);
                af[mt][0] = as[r * PST + c];
                af[mt][1] = as[(r + 8) * PST + c];
                af[mt][2] = as[r * PST + c + 4];
                af[mt][3] = as[(r + 8) * PST + c + 4];
            }
            unsigned bf[8][2];
#pragma unroll
            for (int nt = 0; nt < 8; nt++) {
                int n = wn + nt * 8 + (lane >> 2);
                int c = kk + (lane & 3);
                bf[nt][0] = bs[n * PST + c];
                bf[nt][1] = bs[n * PST + c + 4];
            }
#pragma unroll
            for (int mt = 0; mt < 4; mt++)
#pragma unroll
                for (int nt = 0; nt < 8; nt++)
                    mma8(acc[mt][nt], af[mt], bf[nt]);
        }
    }
#undef ISSUE_TILE

    // ---- epilogue ----
#pragma unroll
    for (int mt = 0; mt < 4; mt++) {
        int row0 = blockM + wm + mt * 16 + (lane >> 2);
        float pp[2]; pp[0] = 0.0f; pp[1] = 0.0f;
        int e0 = 0, e1 = 0;
        if (MODE == EMODE_EF) {
            e0 = rowidx[row0];
            e1 = rowidx[row0 + 8];
        }
#pragma unroll
        for (int h2 = 0; h2 < 2; h2++) {
            int row = row0 + h2 * 8;
#pragma unroll
            for (int nt = 0; nt < 8; nt++) {
                int col = wn + nt * 8 + (lane & 3) * 2;
                float v0 = acc[mt][nt][h2 * 2 + 0];
                float v1 = acc[mt][nt][h2 * 2 + 1];
                if (MODE == EMODE_EF) {
                    v0 = siluf(v0 + bias[col]);
                    v1 = siluf(v1 + bias[col + 1]);
                    float2 st;
                    st.x = __uint_as_float(f2tf(v0));
                    st.y = __uint_as_float(f2tf(v1));
                    *(float2*)&C[(size_t)row * 256 + col] = st;
                    int eidx = h2 ? e1 : e0;
                    red2(&agg[(size_t)eidx * 256 + col], v0, v1);
                } else {
                    v0 = siluf(v0 + bias[col]);
                    v1 = siluf(v1 + bias[col + 1]);
                    pp[h2] += v0 * wc2[col] + v1 * wc2[col + 1];
                }
            }
        }
        if (MODE == EMODE_PHI) {
            pp[0] += __shfl_xor_sync(0xffffffffu, pp[0], 1);
            pp[0] += __shfl_xor_sync(0xffffffffu, pp[0], 2);
            pp[1] += __shfl_xor_sync(0xffffffffu, pp[1], 1);
            pp[1] += __shfl_xor_sync(0xffffffffu, pp[1], 2);
            if ((lane & 3) == 0) {
                atomicAdd(&phi[row0], pp[0]);
                atomicAdd(&phi[row0 + 8], pp[1]);
            }
        }
    }
}

// ---------------- node GEMM (round-2 proven path) ----------------
#define BM 128
#define BN 256
#define BK 32
#define SST 36

enum { MODE_PLAIN = 0, MODE_CAT = 3, MODE_NODE2 = 4 };

template <int MODE>
__global__ void __launch_bounds__(256, 1)
gemm_kernel(const float* __restrict__ A, const float* __restrict__ A2,
            const float* __restrict__ W, const float* __restrict__ bias,
            float* __restrict__ C, int ldc, int M, int K,
            const float* __restrict__ resid)
{
    extern __shared__ unsigned smem[];
    unsigned* Abase = smem;
    unsigned* Bbase = smem + 2 * BM * SST;

    const int tid  = threadIdx.x;
    const int lane = tid & 31;
    const int warp = tid >> 5;
    const int wm = (warp & 1) * 64;
    const int wn = (warp >> 1) * 64;
    const int blockM = blockIdx.x * BM;
    const int blockN = blockIdx.y * BN;
    const int ldr = tid >> 3;
    const int lkq = (tid & 7) * 4;

    float acc[4][8][4];
#pragma unroll
    for (int i = 0; i < 4; i++)
#pragma unroll
        for (int j = 0; j < 8; j++)
#pragma unroll
            for (int q = 0; q < 4; q++) acc[i][j][q] = 0.0f;

    float4 ra[4];
    float4 rb[8];
    const int ktiles = K / BK;

    {
        const int k0 = 0;
#pragma unroll
        for (int i = 0; i < 4; i++) {
            int r = blockM + ldr + i * 32;
            const float* s;
            if (MODE == MODE_CAT)
                s = (k0 + lkq < 256) ? (A + (size_t)r * 256 + k0 + lkq)
                                     : (A2 + (size_t)r * 256 + (k0 + lkq - 256));
            else
                s = A + (size_t)r * K + k0 + lkq;
            ra[i] = (r < M) ? *(const float4*)s : make_float4(0, 0, 0, 0);
        }
#pragma unroll
        for (int i = 0; i < 8; i++) {
            int n = blockN + ldr + i * 32;
            rb[i] = *(const float4*)(W + (size_t)n * K + k0 + lkq);
        }
        unsigned* as = Abase;
        unsigned* bs = Bbase;
#pragma unroll
        for (int i = 0; i < 4; i++) {
            uint4 t; t.x = f2tf(ra[i].x); t.y = f2tf(ra[i].y); t.z = f2tf(ra[i].z); t.w = f2tf(ra[i].w);
            *(uint4*)(as + (ldr + i * 32) * SST + lkq) = t;
        }
#pragma unroll
        for (int i = 0; i < 8; i++) {
            uint4 t; t.x = f2tf(rb[i].x); t.y = f2tf(rb[i].y); t.z = f2tf(rb[i].z); t.w = f2tf(rb[i].w);
            *(uint4*)(bs + (ldr + i * 32) * SST + lkq) = t;
        }
    }
    __syncthreads();

    for (int t = 0; t < ktiles; ++t) {
        if (t + 1 < ktiles) {
            const int k0 = (t + 1) * BK;
#pragma unroll
            for (int i = 0; i < 4; i++) {
                int r = blockM + ldr + i * 32;
                const float* s;
                if (MODE == MODE_CAT)
                    s = (k0 + lkq < 256) ? (A + (size_t)r * 256 + k0 + lkq)
                                         : (A2 + (size_t)r * 256 + (k0 + lkq - 256));
                else
                    s = A + (size_t)r * K + k0 + lkq;
                ra[i] = (r < M) ? *(const float4*)s : make_float4(0, 0, 0, 0);
            }
#pragma unroll
            for (int i = 0; i < 8; i++) {
                int n = blockN + ldr + i * 32;
                rb[i] = *(const float4*)(W + (size_t)n * K + k0 + lkq);
            }
        }
        const unsigned* as = Abase + (t & 1) * BM * SST;
        const unsigned* bs = Bbase + (t & 1) * BN * SST;
#pragma unroll
        for (int kk = 0; kk < BK; kk += 8) {
            unsigned af[4][4];
#pragma unroll
            for (int mt = 0; mt < 4; mt++) {
                int r = wm + mt * 16 + (lane >> 2);
                int c = kk + (lane & 3);
                af[mt][0] = as[r * SST + c];
                af[mt][1] = as[(r + 8) * SST + c];
                af[mt][2] = as[r * SST + c + 4];
                af[mt][3] = as[(r + 8) * SST + c + 4];
            }
            unsigned bf[8][2];
#pragma unroll
            for (int nt = 0; nt < 8; nt++) {
                int n = wn + nt * 8 + (lane >> 2);
                int c = kk + (lane & 3);
                bf[nt][0] = bs[n * SST + c];
                bf[nt][1] = bs[n * SST + c + 4];
            }
#pragma unroll
            for (int mt = 0; mt < 4; mt++)
#pragma unroll
                for (int nt = 0; nt < 8; nt++)
                    mma8(acc[mt][nt], af[mt], bf[nt]);
        }
        if (t + 1 < ktiles) {
            unsigned* asw = Abase + ((t + 1) & 1) * BM * SST;
            unsigned* bsw = Bbase + ((t + 1) & 1) * BN * SST;
#pragma unroll
            for (int i = 0; i < 4; i++) {
                uint4 tt; tt.x = f2tf(ra[i].x); tt.y = f2tf(ra[i].y); tt.z = f2tf(ra[i].z); tt.w = f2tf(ra[i].w);
                *(uint4*)(asw + (ldr + i * 32) * SST + lkq) = tt;
            }
#pragma unroll
            for (int i = 0; i < 8; i++) {
                uint4 tt; tt.x = f2tf(rb[i].x); tt.y = f2tf(rb[i].y); tt.z = f2tf(rb[i].z); tt.w = f2tf(rb[i].w);
                *(uint4*)(bsw + (ldr + i * 32) * SST + lkq) = tt;
            }
            __syncthreads();
        }
    }

#pragma unroll
    for (int mt = 0; mt < 4; mt++) {
#pragma unroll
        for (int h2 = 0; h2 < 2; h2++) {
            int row = blockM + wm + mt * 16 + (lane >> 2) + h2 * 8;
            if (row < M) {
#pragma unroll
                for (int nt = 0; nt < 8; nt++) {
                    int col = blockN + wn + nt * 8 + (lane & 3) * 2;
                    float v0 = acc[mt][nt][h2 * 2 + 0];
                    float v1 = acc[mt][nt][h2 * 2 + 1];
                    if (MODE == MODE_PLAIN) {
                        v0 += bias[col]; v1 += bias[col + 1];
                        *(float2*)&C[(size_t)row * ldc + col] = make_float2(v0, v1);
                    } else if (MODE == MODE_CAT) {
                        v0 = siluf(v0 + bias[col]);
                        v1 = siluf(v1 + bias[col + 1]);
                        *(float2*)&C[(size_t)row * ldc + col] = make_float2(v0, v1);
                    } else {  // MODE_NODE2
                        v0 += bias[col] + resid[(size_t)row * ldc + col];
                        v1 += bias[col + 1] + resid[(size_t)row * ldc + col + 1];
                        *(float2*)&C[(size_t)row * ldc + col] = make_float2(v0, v1);
                    }
                }
            }
        }
    }
}

// ---------------- host ----------------
extern "C" void kernel_launch(void* const* d_in, const int* in_sizes, int n_in,
                              void* d_out, int out_size)
{
    (void)in_sizes; (void)n_in; (void)out_size;
    const float* h     = (const float*)d_in[0];
    const int*   ei    = (const int*)  d_in[1];
    const float* coord = (const float*)d_in[2];
    const float* We1   = (const float*)d_in[3];
    const float* be1   = (const float*)d_in[4];
    const float* We2   = (const float*)d_in[5];
    const float* be2   = (const float*)d_in[6];
    const float* Wn1   = (const float*)d_in[7];
    const float* bn1   = (const float*)d_in[8];
    const float* Wn2   = (const float*)d_in[9];
    const float* bn2   = (const float*)d_in[10];
    const float* Wc1   = (const float*)d_in[11];
    const float* bc1   = (const float*)d_in[12];
    const float* Wc2   = (const float*)d_in[13];
    float* outh = (float*)d_out;
    float* outc = outh + (size_t)NN * 256;

    float *pPQ, *pm, *pef, *pagg, *phmid, *pphi, *pW1ab, *pb512, *pWe2t, *pWc1t;
    cudaGetSymbolAddress((void**)&pPQ,   g_PQ);
    cudaGetSymbolAddress((void**)&pm,    g_m);
    cudaGetSymbolAddress((void**)&pef,   g_ef);
    cudaGetSymbolAddress((void**)&pagg,  g_agg);
    cudaGetSymbolAddress((void**)&phmid, g_hmid);
    cudaGetSymbolAddress((void**)&pphi,  g_phi);
    cudaGetSymbolAddress((void**)&pW1ab, g_W1ab);
    cudaGetSymbolAddress((void**)&pb512, g_b512);
    cudaGetSymbolAddress((void**)&pWe2t, g_We2t);
    cudaGetSymbolAddress((void**)&pWc1t, g_Wc1t);

    const int SMEMB  = (2 * BM * SST + 2 * BN * SST) * 4;  // 110592
    const int ESMEMB = ESMEM_WORDS * 4;                    // 165888
    cudaFuncSetAttribute((const void*)gemm_kernel<MODE_PLAIN>, cudaFuncAttributeMaxDynamicSharedMemorySize, SMEMB);
    cudaFuncSetAttribute((const void*)gemm_kernel<MODE_CAT>,   cudaFuncAttributeMaxDynamicSharedMemorySize, SMEMB);
    cudaFuncSetAttribute((const void*)gemm_kernel<MODE_NODE2>, cudaFuncAttributeMaxDynamicSharedMemorySize, SMEMB);
    cudaFuncSetAttribute((const void*)egemm<EMODE_EF>,  cudaFuncAttributeMaxDynamicSharedMemorySize, ESMEMB);
    cudaFuncSetAttribute((const void*)egemm<EMODE_PHI>, cudaFuncAttributeMaxDynamicSharedMemorySize, ESMEMB);

    pack_weights<<<512, 256>>>(We1, be1, We2, Wc1);
    zero_scratch<<<50000, 256>>>();

    // PQ = h @ [We1a;We1b]^T + [be1;0]
    gemm_kernel<MODE_PLAIN><<<dim3((NN + BM - 1) / BM, 2), 256, SMEMB>>>(
        h, nullptr, pW1ab, pb512, pPQ, 512, NN, 256, nullptr);

    // m = tf32(SiLU(P[row]+Q[col]+radial*wr)); counts cnt[row]
    edge_m_kernel<<<(NE + 7) / 8, 256>>>(ei, coord);

    // ef = tf32(SiLU(m @ We2^T + be2)); agg[row] += SiLU vals
    egemm<EMODE_EF><<<NE / 128, 256, ESMEMB>>>(
        pm, pWe2t, be2, pef, ei, pagg, nullptr, nullptr);

    // phi = SiLU(ef @ Wc1^T + bc1) . wc2
    egemm<EMODE_PHI><<<NE / 128, 256, ESMEMB>>>(
        pef, pWc1t, bc1, nullptr, nullptr, nullptr, Wc2, pphi);

    // coord aggregation + output
    edge_coord_kernel<<<(NE + 255) / 256, 256>>>(ei, coord);
    coord_final_kernel<<<(NN + 255) / 256, 256>>>(coord, outc);

    // hmid = SiLU([h | agg] @ Wn1^T + bn1)
    gemm_kernel<MODE_CAT><<<dim3((NN + BM - 1) / BM, 1), 256, SMEMB>>>(
        h, pagg, Wn1, bn1, phmid, 256, NN, 512, nullptr);

    // h_out = hmid @ Wn2^T + bn2 + h
    gemm_kernel<MODE_NODE2><<<dim3((NN + BM - 1) / BM, 1), 256, SMEMB>>>(
        phmid, nullptr, Wn2, bn2, outh, 256, NN, 256, h);
}